// round 7
// baseline (speedup 1.0000x reference)
#include <cuda_runtime.h>
#include <cuda_bf16.h>
#include <cstdint>

// Problem constants
#define M_ROWS 16384      // 8 * 2048
#define D_IN   512
#define NB     8
#define KTOT   4608       // 512 (relu base) + 512*8 (bs+rbf)
#define N_OUT  512

// GEMM tiling (mma.sync path, base compute_100 features only)
#define BM 128
#define BN 64
#define BK 32                       // bf16 K per stage
#define NITER (KTOT / BK)           // 144
#define NSTAGE 3
#define ASTRIDE 80                  // bytes per smem row: 32 bf16 (64B) + 16B pad
#define A_BYTES (BM * ASTRIDE)      // 10240
#define B_BYTES (BN * ASTRIDE)      // 5120
#define STG_BYTES (2 * A_BYTES + 2 * B_BYTES)   // 30720: Ah | Al | Bh | Bl
#define SMEM_TOTAL (NSTAGE * STG_BYTES)         // 92160

// Scratch: bf16 hi/lo split feature + weight matrices
__device__ __nv_bfloat16 g_Fh[(size_t)M_ROWS * KTOT];
__device__ __nv_bfloat16 g_Fl[(size_t)M_ROWS * KTOT];
__device__ __nv_bfloat16 g_Wh[(size_t)N_OUT * KTOT];
__device__ __nv_bfloat16 g_Wl[(size_t)N_OUT * KTOT];

// ---------------------------------------------------------------------------
// PTX helpers — all base sm_80-class features, valid on compute_100
// ---------------------------------------------------------------------------
__device__ __forceinline__ uint32_t smem_u32(const void* p) {
    uint32_t a;
    asm("{ .reg .u64 t; cvta.to.shared.u64 t, %1; cvt.u32.u64 %0, t; }" : "=r"(a) : "l"(p));
    return a;
}
__device__ __forceinline__ void cp_async16(uint32_t s, const void* g) {
    asm volatile("cp.async.cg.shared.global [%0], [%1], 16;" :: "r"(s), "l"(g));
}
#define CP_COMMIT() asm volatile("cp.async.commit_group;" ::: "memory")
#define CP_WAIT(n)  asm volatile("cp.async.wait_group %0;" :: "n"(n) : "memory")

__device__ __forceinline__ void ldsm4(uint32_t* r, uint32_t addr) {
    asm volatile("ldmatrix.sync.aligned.m8n8.x4.shared.b16 {%0,%1,%2,%3}, [%4];"
                 : "=r"(r[0]), "=r"(r[1]), "=r"(r[2]), "=r"(r[3]) : "r"(addr));
}
__device__ __forceinline__ void mma16816(float* c, const uint32_t* a,
                                         uint32_t b0, uint32_t b1) {
    asm volatile("mma.sync.aligned.m16n8k16.row.col.f32.bf16.bf16.f32 "
                 "{%0,%1,%2,%3}, {%4,%5,%6,%7}, {%8,%9}, {%0,%1,%2,%3};"
                 : "+f"(c[0]), "+f"(c[1]), "+f"(c[2]), "+f"(c[3])
                 : "r"(a[0]), "r"(a[1]), "r"(a[2]), "r"(a[3]), "r"(b0), "r"(b1));
}

// ---------------------------------------------------------------------------
// Kernel 0: split weights to bf16 hi/lo, concat [base | spline]
// ---------------------------------------------------------------------------
__global__ void prep_kernel(const float* __restrict__ bw,
                            const float* __restrict__ sw) {
    int o = blockIdx.x;           // 0..511
    int t = threadIdx.x;          // 256 threads
    size_t rb = (size_t)o * KTOT;
    for (int k = t; k < D_IN; k += 256) {
        float v = bw[o * D_IN + k];
        __nv_bfloat16 h = __float2bfloat16(v);
        g_Wh[rb + k] = h;
        g_Wl[rb + k] = __float2bfloat16(v - __bfloat162float(h));
    }
    const float* sp = sw + (size_t)o * (D_IN * NB);
    for (int k = t; k < D_IN * NB; k += 256) {
        float v = sp[k];
        __nv_bfloat16 h = __float2bfloat16(v);
        g_Wh[rb + D_IN + k] = h;
        g_Wl[rb + D_IN + k] = __float2bfloat16(v - __bfloat162float(h));
    }
}

// ---------------------------------------------------------------------------
// Kernel 1: layernorm + features, written as bf16 hi/lo split
// ---------------------------------------------------------------------------
__global__ void feat_kernel(const float* __restrict__ x,
                            const float* __restrict__ gamma,
                            const float* __restrict__ beta) {
    const int row = blockIdx.x;
    const int t   = threadIdx.x;        // 256 threads, 2 dims each
    const float* xr = x + (size_t)row * D_IN;

    float v0 = xr[t];
    float v1 = xr[t + 256];
    float s  = v0 + v1;
    float s2 = v0 * v0 + v1 * v1;
    #pragma unroll
    for (int off = 16; off; off >>= 1) {
        s  += __shfl_xor_sync(0xFFFFFFFFu, s,  off);
        s2 += __shfl_xor_sync(0xFFFFFFFFu, s2, off);
    }
    __shared__ float red[16];
    __shared__ float mu_s, rstd_s;
    int wid = t >> 5, lane = t & 31;
    if (lane == 0) { red[wid] = s; red[8 + wid] = s2; }
    __syncthreads();
    if (t == 0) {
        float ts = 0.f, ts2 = 0.f;
        #pragma unroll
        for (int i = 0; i < 8; i++) { ts += red[i]; ts2 += red[8 + i]; }
        float mu  = ts * (1.0f / 512.0f);
        float var = ts2 * (1.0f / 512.0f) - mu * mu;
        mu_s   = mu;
        rstd_s = rsqrtf(var + 1e-5f);
    }
    __syncthreads();
    const float mu = mu_s, rstd = rstd_s;

    size_t rb = (size_t)row * KTOT;
    const float H    = 3.0f / 5.0f;
    const float INVD = 7.0f / 3.0f;

    #pragma unroll
    for (int half = 0; half < 2; half++) {
        const int   d  = t + half * 256;
        const float xv = half ? v1 : v0;
        const float xn = (xv - mu) * rstd * gamma[d] + beta[d];

        float rl = fmaxf(xn, 0.0f);
        __nv_bfloat16 rh = __float2bfloat16(rl);
        g_Fh[rb + d] = rh;
        g_Fl[rb + d] = __float2bfloat16(rl - __bfloat162float(rh));

        // Cox-de Boor, uniform knots t_i = (i-3)*H - 1.5, i=0..11
        float b[11];
        #pragma unroll
        for (int i = 0; i < 11; i++) {
            float t0 = (float)(i - 3) * H - 1.5f;
            float t1 = (float)(i - 2) * H - 1.5f;
            b[i] = (xn >= t0 && xn < t1) ? 1.0f : 0.0f;
        }
        #pragma unroll
        for (int k = 1; k <= 3; k++) {
            const float inv = 1.0f / ((float)k * H);
            #pragma unroll
            for (int i = 0; i + k < 11; i++) {
                float ti   = (float)(i - 3) * H - 1.5f;
                float tik1 = (float)(i + k - 2) * H - 1.5f;
                float left  = (xn - ti) * inv;
                float right = (tik1 - xn) * inv;
                b[i] = left * b[i] + right * b[i + 1];
            }
        }

        __nv_bfloat16 oh[8], ol[8];
        #pragma unroll
        for (int j = 0; j < 8; j++) {
            float g = -1.5f + (float)j * (3.0f / 7.0f);
            float u = (xn - g) * INVD;
            float f = b[j] + __expf(-u * u);
            __nv_bfloat16 h = __float2bfloat16(f);
            oh[j] = h;
            ol[j] = __float2bfloat16(f - __bfloat162float(h));
        }
        *(uint4*)(&g_Fh[rb + D_IN + (size_t)d * NB]) = *(const uint4*)oh;
        *(uint4*)(&g_Fl[rb + D_IN + (size_t)d * NB]) = *(const uint4*)ol;
    }
}

// ---------------------------------------------------------------------------
// Kernel 2: mma.sync bf16 GEMM with hi/lo compensation
//   C = Fh*Wh^T + Fh*Wl^T + Fl*Wh^T   (fp32 accumulators)
// CTA: 128(M) x 64(N), 4 warps, warp tile 32x64.
// 3-stage cp.async ring, ONE __syncthreads per iteration, 2 CTAs/SM.
// ---------------------------------------------------------------------------
__global__ __launch_bounds__(128, 2) void gemm_kernel(float* __restrict__ C) {
    extern __shared__ char smem[];
    const uint32_t sbase = smem_u32(smem);
    const int t    = threadIdx.x;
    const int wm   = t >> 5;            // warp index = m sub-tile (0..3)
    const int lane = t & 31;
    const int m0   = blockIdx.y * BM;
    const int n0   = blockIdx.x * BN;

    const __nv_bfloat16* Ah_g = g_Fh + (size_t)m0 * KTOT;
    const __nv_bfloat16* Al_g = g_Fl + (size_t)m0 * KTOT;
    const __nv_bfloat16* Bh_g = g_Wh + (size_t)n0 * KTOT;
    const __nv_bfloat16* Bl_g = g_Wl + (size_t)n0 * KTOT;

    // Per-lane ldmatrix base offsets
    //   A (x4 over m16 x k16): row=(l>>3 &1)*8 + (l&7), kchunk=(l>>4)*16B
    const uint32_t a_off = (uint32_t)((((lane >> 3) & 1) * 8 + (lane & 7)) * ASTRIDE
                                      + (lane >> 4) * 16);
    //   B (x4 over two n8 blocks x k16): nrow=(l>>4 &1)*8 + (l&7), kchunk=(l>>3 &1)*16B
    const uint32_t b_off = (uint32_t)((((lane >> 4) & 1) * 8 + (lane & 7)) * ASTRIDE
                                      + ((lane >> 3) & 1) * 16);

    float acc[2][8][4];
    #pragma unroll
    for (int i = 0; i < 2; i++)
        #pragma unroll
        for (int j = 0; j < 8; j++)
            #pragma unroll
            for (int q = 0; q < 4; q++) acc[i][j][q] = 0.0f;

    // ---- stage loader: 12 cp.async of 16B per thread ----
    auto load_stage = [&](int st, int kc) {
        const uint32_t stage = sbase + st * STG_BYTES;
        #pragma unroll
        for (int r = 0; r < 4; r++) {
            int u = t + r * 128;               // 0..511
            int row = u >> 2, ch = u & 3;
            size_t go = (size_t)row * KTOT + kc + ch * 8;
            uint32_t so = (uint32_t)(row * ASTRIDE + ch * 16);
            cp_async16(stage + so,            Ah_g + go);
            cp_async16(stage + A_BYTES + so,  Al_g + go);
        }
        #pragma unroll
        for (int r = 0; r < 2; r++) {
            int u = t + r * 128;               // 0..255
            int row = u >> 2, ch = u & 3;
            size_t go = (size_t)row * KTOT + kc + ch * 8;
            uint32_t so = (uint32_t)(row * ASTRIDE + ch * 16);
            cp_async16(stage + 2 * A_BYTES + so,            Bh_g + go);
            cp_async16(stage + 2 * A_BYTES + B_BYTES + so,  Bl_g + go);
        }
    };

    // Prologue: fill stages 0 and 1
    load_stage(0, 0);
    CP_COMMIT();
    load_stage(1, BK);
    CP_COMMIT();

    int stage_rd = 0;      // stage holding K-chunk i
    int stage_wr = 2;      // stage to fill with K-chunk i+2

    for (int i = 0; i < NITER; i++) {
        // Stage i ready: all groups except (possibly) the newest are complete.
        if (i == NITER - 1) { CP_WAIT(0); } else { CP_WAIT(1); }
        // Orders: (a) stage-i loads visible to all warps; (b) all warps done
        // reading stage i-1 (≡ stage_wr) before we overwrite it below.
        __syncthreads();

        if (i + 2 < NITER) {
            load_stage(stage_wr, (i + 2) * BK);
            CP_COMMIT();
        }

        const uint32_t stage = sbase + stage_rd * STG_BYTES;
        const uint32_t sAh = stage;
        const uint32_t sAl = stage + A_BYTES;
        const uint32_t sBh = stage + 2 * A_BYTES;
        const uint32_t sBl = stage + 2 * A_BYTES + B_BYTES;
        const uint32_t awarp = (uint32_t)(wm * 32 * ASTRIDE);

        #pragma unroll
        for (int s = 0; s < 2; s++) {       // two k16 steps
            const uint32_t ks = (uint32_t)(s * 32);   // 16 bf16 = 32 bytes
            uint32_t ah[2][4], al[2][4], bh[4][4], bl[4][4];
            #pragma unroll
            for (int im = 0; im < 2; im++) {
                ldsm4(ah[im], sAh + awarp + (uint32_t)(im * 16 * ASTRIDE) + a_off + ks);
                ldsm4(al[im], sAl + awarp + (uint32_t)(im * 16 * ASTRIDE) + a_off + ks);
            }
            #pragma unroll
            for (int jj = 0; jj < 4; jj++) {
                ldsm4(bh[jj], sBh + (uint32_t)(jj * 16 * ASTRIDE) + b_off + ks);
                ldsm4(bl[jj], sBl + (uint32_t)(jj * 16 * ASTRIDE) + b_off + ks);
            }
            #pragma unroll
            for (int im = 0; im < 2; im++)
                #pragma unroll
                for (int j = 0; j < 8; j++) {
                    uint32_t bh0 = bh[j >> 1][(j & 1) * 2];
                    uint32_t bh1 = bh[j >> 1][(j & 1) * 2 + 1];
                    uint32_t bl0 = bl[j >> 1][(j & 1) * 2];
                    uint32_t bl1 = bl[j >> 1][(j & 1) * 2 + 1];
                    mma16816(acc[im][j], ah[im], bh0, bh1);   // hi*hi
                    mma16816(acc[im][j], ah[im], bl0, bl1);   // hi*lo
                    mma16816(acc[im][j], al[im], bh0, bh1);   // lo*hi
                }
        }

        stage_rd = (stage_rd == NSTAGE - 1) ? 0 : stage_rd + 1;
        stage_wr = (stage_wr == NSTAGE - 1) ? 0 : stage_wr + 1;
    }

    // Writeout: C row = m0 + wm*32 + im*16 + lane/4 (+8), col = n0 + j*8 + (lane%4)*2
    #pragma unroll
    for (int im = 0; im < 2; im++) {
        int r0 = m0 + wm * 32 + im * 16 + (lane >> 2);
        #pragma unroll
        for (int j = 0; j < 8; j++) {
            int cc = n0 + j * 8 + (lane & 3) * 2;
            *(float2*)(C + (size_t)r0 * N_OUT + cc) =
                make_float2(acc[im][j][0], acc[im][j][1]);
            *(float2*)(C + (size_t)(r0 + 8) * N_OUT + cc) =
                make_float2(acc[im][j][2], acc[im][j][3]);
        }
    }
}

// ---------------------------------------------------------------------------
extern "C" void kernel_launch(void* const* d_in, const int* in_sizes, int n_in,
                              void* d_out, int out_size) {
    const float* x        = (const float*)d_in[0];
    const float* ln_gamma = (const float*)d_in[1];
    const float* ln_beta  = (const float*)d_in[2];
    const float* base_w   = (const float*)d_in[3];
    const float* spline_w = (const float*)d_in[4];
    (void)in_sizes; (void)n_in; (void)out_size;

    cudaFuncSetAttribute(gemm_kernel, cudaFuncAttributeMaxDynamicSharedMemorySize, SMEM_TOTAL);

    prep_kernel<<<N_OUT, 256>>>(base_w, spline_w);
    feat_kernel<<<M_ROWS, 256>>>(x, ln_gamma, ln_beta);
    dim3 grid(N_OUT / BN, M_ROWS / BM);   // (8, 128)
    gemm_kernel<<<grid, 128, SMEM_TOTAL>>>((float*)d_out);
}

// round 9
// speedup vs baseline: 1.6949x; 1.6949x over previous
#include <cuda_runtime.h>
#include <cuda_bf16.h>
#include <cstdint>

// Problem constants
#define M_ROWS 16384      // 8 * 2048
#define D_IN   512
#define NB     8
#define KTOT   4608       // 512 (relu base) + 512*8 (bs+rbf)
#define N_OUT  512

// GEMM tiling (int8 mma.sync m16n8k32 path)
#define BM 128
#define BN 64
#define BK 64                       // int8 K elements (=bytes) per stage
#define NITER (KTOT / BK)           // 72
#define ASTRIDE 80                  // bytes per smem row: 64B data + 16B pad
#define A_BYTES (BM * ASTRIDE)      // 10240
#define B_BYTES (BN * ASTRIDE)      // 5120
#define STG_BYTES (2 * A_BYTES + 2 * B_BYTES)   // 30720: A1 | A0 | B1 | B0
#define SMEM_TOTAL (2 * STG_BYTES)              // 61440

// Scratch: int8 2-slice fixed-point matrices + per-row scales.
// __align__(16): cp.async 16B and uint2 stores require aligned bases.
__device__ __align__(16) int8_t g_F1[(size_t)M_ROWS * KTOT];
__device__ __align__(16) int8_t g_F0[(size_t)M_ROWS * KTOT];
__device__ __align__(16) int8_t g_W1[(size_t)N_OUT * KTOT];
__device__ __align__(16) int8_t g_W0[(size_t)N_OUT * KTOT];
__device__ float  g_sF[M_ROWS];
__device__ float  g_sW[N_OUT];

// ---------------------------------------------------------------------------
// PTX helpers — base sm_80-class features, valid on compute_100
// ---------------------------------------------------------------------------
__device__ __forceinline__ uint32_t smem_u32(const void* p) {
    uint32_t a;
    asm("{ .reg .u64 t; cvta.to.shared.u64 t, %1; cvt.u32.u64 %0, t; }" : "=r"(a) : "l"(p));
    return a;
}
__device__ __forceinline__ void cp_async16(uint32_t s, const void* g) {
    asm volatile("cp.async.cg.shared.global [%0], [%1], 16;" :: "r"(s), "l"(g));
}
#define CP_COMMIT() asm volatile("cp.async.commit_group;" ::: "memory")
#define CP_WAIT(n)  asm volatile("cp.async.wait_group %0;" :: "n"(n) : "memory")

__device__ __forceinline__ void ldsm4(uint32_t* r, uint32_t addr) {
    asm volatile("ldmatrix.sync.aligned.m8n8.x4.shared.b16 {%0,%1,%2,%3}, [%4];"
                 : "=r"(r[0]), "=r"(r[1]), "=r"(r[2]), "=r"(r[3]) : "r"(addr));
}
// s8 mma m16n8k32, s32 accumulate
__device__ __forceinline__ void imma16832(int* c, const uint32_t* a,
                                          uint32_t b0, uint32_t b1) {
    asm volatile("mma.sync.aligned.m16n8k32.row.col.s32.s8.s8.s32 "
                 "{%0,%1,%2,%3}, {%4,%5,%6,%7}, {%8,%9}, {%0,%1,%2,%3};"
                 : "+r"(c[0]), "+r"(c[1]), "+r"(c[2]), "+r"(c[3])
                 : "r"(a[0]), "r"(a[1]), "r"(a[2]), "r"(a[3]), "r"(b0), "r"(b1));
}

// 2-slice int8 quantization: q in [-16256, 16256] -> h in [-127,127], l in [-64,64]
__device__ __forceinline__ void quant2(float q, int& h, int& l) {
    h = __float2int_rn(q * 0.0078125f);          // q/128
    l = __float2int_rn(q - 128.0f * (float)h);
}

// ---------------------------------------------------------------------------
// Kernel 0: quantize weights to 2-slice int8, per-output-row scale
// ---------------------------------------------------------------------------
__global__ void prep_kernel(const float* __restrict__ bw,
                            const float* __restrict__ sw) {
    int o = blockIdx.x;           // 0..511
    int t = threadIdx.x;          // 256 threads
    size_t rb = (size_t)o * KTOT;
    const float* sp = sw + (size_t)o * (D_IN * NB);

    // Pass 1: row max |W|
    float m = 0.0f;
    for (int k = t; k < D_IN; k += 256) m = fmaxf(m, fabsf(bw[o * D_IN + k]));
    for (int k = t; k < D_IN * NB; k += 256) m = fmaxf(m, fabsf(sp[k]));
    #pragma unroll
    for (int off = 16; off; off >>= 1)
        m = fmaxf(m, __shfl_xor_sync(0xFFFFFFFFu, m, off));
    __shared__ float red[8];
    __shared__ float s_inv;
    if ((t & 31) == 0) red[t >> 5] = m;
    __syncthreads();
    if (t == 0) {
        float mx = 0.0f;
        #pragma unroll
        for (int i = 0; i < 8; i++) mx = fmaxf(mx, red[i]);
        float sW = fmaxf(mx, 1e-20f) * (1.0f / 16256.0f);
        g_sW[o] = sW;
        s_inv = 1.0f / sW;
    }
    __syncthreads();
    const float inv = s_inv;

    // Pass 2: quantize
    for (int k = t; k < D_IN; k += 256) {
        int h, l; quant2(bw[o * D_IN + k] * inv, h, l);
        g_W1[rb + k] = (int8_t)h; g_W0[rb + k] = (int8_t)l;
    }
    for (int k = t; k < D_IN * NB; k += 256) {
        int h, l; quant2(sp[k] * inv, h, l);
        g_W1[rb + D_IN + k] = (int8_t)h; g_W0[rb + D_IN + k] = (int8_t)l;
    }
}

// ---------------------------------------------------------------------------
// Kernel 1: layernorm + features -> 2-slice int8 with per-row scale
// ---------------------------------------------------------------------------
__global__ void feat_kernel(const float* __restrict__ x,
                            const float* __restrict__ gamma,
                            const float* __restrict__ beta) {
    const int row = blockIdx.x;
    const int t   = threadIdx.x;        // 256 threads, 2 dims each
    const float* xr = x + (size_t)row * D_IN;

    float v0 = xr[t];
    float v1 = xr[t + 256];
    float s  = v0 + v1;
    float s2 = v0 * v0 + v1 * v1;
    #pragma unroll
    for (int off = 16; off; off >>= 1) {
        s  += __shfl_xor_sync(0xFFFFFFFFu, s,  off);
        s2 += __shfl_xor_sync(0xFFFFFFFFu, s2, off);
    }
    __shared__ float red[16];
    __shared__ float mu_s, rstd_s, sinv_s;
    int wid = t >> 5, lane = t & 31;
    if (lane == 0) { red[wid] = s; red[8 + wid] = s2; }
    __syncthreads();
    if (t == 0) {
        float ts = 0.f, ts2 = 0.f;
        #pragma unroll
        for (int i = 0; i < 8; i++) { ts += red[i]; ts2 += red[8 + i]; }
        float mu  = ts * (1.0f / 512.0f);
        float var = ts2 * (1.0f / 512.0f) - mu * mu;
        mu_s   = mu;
        rstd_s = rsqrtf(var + 1e-5f);
    }
    __syncthreads();
    const float mu = mu_s, rstd = rstd_s;

    const float H    = 3.0f / 5.0f;
    const float INVD = 7.0f / 3.0f;

    // Compute all 18 features of this thread's 2 dims, track local max
    float fr[2];         // relu
    float fs[2][8];      // bspline + rbf
    float lmax = 0.0f;

    #pragma unroll
    for (int half = 0; half < 2; half++) {
        const int   d  = t + half * 256;
        const float xv = half ? v1 : v0;
        const float xn = (xv - mu) * rstd * gamma[d] + beta[d];

        fr[half] = fmaxf(xn, 0.0f);
        lmax = fmaxf(lmax, fr[half]);

        // Cox-de Boor, uniform knots t_i = (i-3)*H - 1.5, i=0..11
        float b[11];
        #pragma unroll
        for (int i = 0; i < 11; i++) {
            float t0 = (float)(i - 3) * H - 1.5f;
            float t1 = (float)(i - 2) * H - 1.5f;
            b[i] = (xn >= t0 && xn < t1) ? 1.0f : 0.0f;
        }
        #pragma unroll
        for (int k = 1; k <= 3; k++) {
            const float inv = 1.0f / ((float)k * H);
            #pragma unroll
            for (int i = 0; i + k < 11; i++) {
                float ti   = (float)(i - 3) * H - 1.5f;
                float tik1 = (float)(i + k - 2) * H - 1.5f;
                float left  = (xn - ti) * inv;
                float right = (tik1 - xn) * inv;
                b[i] = left * b[i] + right * b[i + 1];
            }
        }
        #pragma unroll
        for (int j = 0; j < 8; j++) {
            float g = -1.5f + (float)j * (3.0f / 7.0f);
            float u = (xn - g) * INVD;
            float f = b[j] + __expf(-u * u);
            fs[half][j] = f;
            lmax = fmaxf(lmax, f);
        }
    }

    // Block max -> per-row scale
    #pragma unroll
    for (int off = 16; off; off >>= 1)
        lmax = fmaxf(lmax, __shfl_xor_sync(0xFFFFFFFFu, lmax, off));
    if (lane == 0) red[wid] = lmax;
    __syncthreads();
    if (t == 0) {
        float mx = 0.0f;
        #pragma unroll
        for (int i = 0; i < 8; i++) mx = fmaxf(mx, red[i]);
        float sF = fmaxf(mx, 1e-20f) * (1.0f / 16256.0f);
        g_sF[row] = sF;
        sinv_s = 1.0f / sF;
    }
    __syncthreads();
    const float inv = sinv_s;

    size_t rb = (size_t)row * KTOT;
    #pragma unroll
    for (int half = 0; half < 2; half++) {
        const int d = t + half * 256;
        int h, l;
        quant2(fr[half] * inv, h, l);
        g_F1[rb + d] = (int8_t)h;
        g_F0[rb + d] = (int8_t)l;

        uint32_t h_lo = 0, h_hi = 0, l_lo = 0, l_hi = 0;
        #pragma unroll
        for (int j = 0; j < 4; j++) {
            int hh, ll;
            quant2(fs[half][j] * inv, hh, ll);
            h_lo |= (uint32_t)(uint8_t)(int8_t)hh << (8 * j);
            l_lo |= (uint32_t)(uint8_t)(int8_t)ll << (8 * j);
            quant2(fs[half][j + 4] * inv, hh, ll);
            h_hi |= (uint32_t)(uint8_t)(int8_t)hh << (8 * j);
            l_hi |= (uint32_t)(uint8_t)(int8_t)ll << (8 * j);
        }
        // 8-byte aligned stores (base 16B-aligned; 512 + 8d is 8-aligned)
        *(uint2*)(g_F1 + rb + D_IN + (size_t)d * NB) = make_uint2(h_lo, h_hi);
        *(uint2*)(g_F0 + rb + D_IN + (size_t)d * NB) = make_uint2(l_lo, l_hi);
    }
}

// ---------------------------------------------------------------------------
// Kernel 2: int8 m16n8k32 GEMM, 2-slice compensation
//   C = sF*sW * (16384*F1W1 + 128*(F1W0 + F0W1))   [F0W0 dropped]
// CTA: 128(M) x 64(N), 4 warps, warp tile 32x64. 2-stage cp.async pipeline
// (R5 scheduling verbatim — the fastest measured variant).
// ---------------------------------------------------------------------------
__global__ __launch_bounds__(128, 2) void gemm_kernel(float* __restrict__ C) {
    extern __shared__ char smem[];
    const uint32_t sbase = smem_u32(smem);
    const int t    = threadIdx.x;
    const int wm   = t >> 5;            // warp index = m sub-tile (0..3)
    const int lane = t & 31;
    const int m0   = blockIdx.y * BM;
    const int n0   = blockIdx.x * BN;

    const int8_t* A1_g = g_F1 + (size_t)m0 * KTOT;
    const int8_t* A0_g = g_F0 + (size_t)m0 * KTOT;
    const int8_t* B1_g = g_W1 + (size_t)n0 * KTOT;
    const int8_t* B0_g = g_W0 + (size_t)n0 * KTOT;

    // Per-lane ldmatrix base offsets (s8 k32 wants the same (row, 16B-chunk)
    // distribution as bf16 k16 — verified against the PTX fragment spec):
    const uint32_t a_off = (uint32_t)((((lane >> 3) & 1) * 8 + (lane & 7)) * ASTRIDE
                                      + (lane >> 4) * 16);
    const uint32_t b_off = (uint32_t)((((lane >> 4) & 1) * 8 + (lane & 7)) * ASTRIDE
                                      + ((lane >> 3) & 1) * 16);

    int accA[2][8][4];   // F1*W1
    int accB[2][8][4];   // F1*W0 + F0*W1
    #pragma unroll
    for (int i = 0; i < 2; i++)
        #pragma unroll
        for (int j = 0; j < 8; j++)
            #pragma unroll
            for (int q = 0; q < 4; q++) { accA[i][j][q] = 0; accB[i][j][q] = 0; }

    // ---- stage loader: 12 cp.async of 16B per thread ----
    auto load_stage = [&](int st, int kc) {
        const uint32_t stage = sbase + st * STG_BYTES;
        #pragma unroll
        for (int r = 0; r < 4; r++) {
            int u = t + r * 128;               // 0..511
            int row = u >> 2, ch = u & 3;
            size_t go = (size_t)row * KTOT + kc + ch * 16;
            uint32_t so = (uint32_t)(row * ASTRIDE + ch * 16);
            cp_async16(stage + so,            A1_g + go);
            cp_async16(stage + A_BYTES + so,  A0_g + go);
        }
        #pragma unroll
        for (int r = 0; r < 2; r++) {
            int u = t + r * 128;               // 0..255
            int row = u >> 2, ch = u & 3;
            size_t go = (size_t)row * KTOT + kc + ch * 16;
            uint32_t so = (uint32_t)(row * ASTRIDE + ch * 16);
            cp_async16(stage + 2 * A_BYTES + so,            B1_g + go);
            cp_async16(stage + 2 * A_BYTES + B_BYTES + so,  B0_g + go);
        }
    };

    load_stage(0, 0);
    CP_COMMIT();

    for (int i = 0; i < NITER; i++) {
        if (i + 1 < NITER) {
            load_stage((i + 1) & 1, (i + 1) * BK);
            CP_COMMIT();
            CP_WAIT(1);
        } else {
            CP_WAIT(0);
        }
        __syncthreads();

        const uint32_t stage = sbase + (i & 1) * STG_BYTES;
        const uint32_t sA1 = stage;
        const uint32_t sA0 = stage + A_BYTES;
        const uint32_t sB1 = stage + 2 * A_BYTES;
        const uint32_t sB0 = stage + 2 * A_BYTES + B_BYTES;
        const uint32_t awarp = (uint32_t)(wm * 32 * ASTRIDE);

        #pragma unroll
        for (int s = 0; s < 2; s++) {       // two k32 steps
            const uint32_t ks = (uint32_t)(s * 32);   // 32 int8 = 32 bytes
            uint32_t a1[2][4], a0[2][4], b1[4][4], b0[4][4];
            #pragma unroll
            for (int im = 0; im < 2; im++) {
                ldsm4(a1[im], sA1 + awarp + (uint32_t)(im * 16 * ASTRIDE) + a_off + ks);
                ldsm4(a0[im], sA0 + awarp + (uint32_t)(im * 16 * ASTRIDE) + a_off + ks);
            }
            #pragma unroll
            for (int jj = 0; jj < 4; jj++) {
                ldsm4(b1[jj], sB1 + (uint32_t)(jj * 16 * ASTRIDE) + b_off + ks);
                ldsm4(b0[jj], sB0 + (uint32_t)(jj * 16 * ASTRIDE) + b_off + ks);
            }
            #pragma unroll
            for (int im = 0; im < 2; im++)
                #pragma unroll
                for (int j = 0; j < 8; j++) {
                    uint32_t bh0 = b1[j >> 1][(j & 1) * 2];
                    uint32_t bh1 = b1[j >> 1][(j & 1) * 2 + 1];
                    uint32_t bl0 = b0[j >> 1][(j & 1) * 2];
                    uint32_t bl1 = b0[j >> 1][(j & 1) * 2 + 1];
                    imma16832(accA[im][j], a1[im], bh0, bh1);   // F1*W1
                    imma16832(accB[im][j], a1[im], bl0, bl1);   // F1*W0
                    imma16832(accB[im][j], a0[im], bh0, bh1);   // F0*W1
                }
        }
        __syncthreads();   // all warps done with this stage before refill
    }

    // Writeout with scale combine:
    //   C = (16384*accA + 128*accB) * sF[row] * sW[col]
    #pragma unroll
    for (int im = 0; im < 2; im++) {
        int r0 = m0 + wm * 32 + im * 16 + (lane >> 2);
        float sf0 = g_sF[r0];
        float sf1 = g_sF[r0 + 8];
        #pragma unroll
        for (int j = 0; j < 8; j++) {
            int cc = n0 + j * 8 + (lane & 3) * 2;
            float sw0 = g_sW[cc], sw1 = g_sW[cc + 1];
            float v0 = 16384.0f * (float)accA[im][j][0] + 128.0f * (float)accB[im][j][0];
            float v1 = 16384.0f * (float)accA[im][j][1] + 128.0f * (float)accB[im][j][1];
            float v2 = 16384.0f * (float)accA[im][j][2] + 128.0f * (float)accB[im][j][2];
            float v3 = 16384.0f * (float)accA[im][j][3] + 128.0f * (float)accB[im][j][3];
            *(float2*)(C + (size_t)r0 * N_OUT + cc) =
                make_float2(v0 * sf0 * sw0, v1 * sf0 * sw1);
            *(float2*)(C + (size_t)(r0 + 8) * N_OUT + cc) =
                make_float2(v2 * sf1 * sw0, v3 * sf1 * sw1);
        }
    }
}

// ---------------------------------------------------------------------------
extern "C" void kernel_launch(void* const* d_in, const int* in_sizes, int n_in,
                              void* d_out, int out_size) {
    const float* x        = (const float*)d_in[0];
    const float* ln_gamma = (const float*)d_in[1];
    const float* ln_beta  = (const float*)d_in[2];
    const float* base_w   = (const float*)d_in[3];
    const float* spline_w = (const float*)d_in[4];
    (void)in_sizes; (void)n_in; (void)out_size;

    cudaFuncSetAttribute(gemm_kernel, cudaFuncAttributeMaxDynamicSharedMemorySize, SMEM_TOTAL);

    prep_kernel<<<N_OUT, 256>>>(base_w, spline_w);
    feat_kernel<<<M_ROWS, 256>>>(x, ln_gamma, ln_beta);
    dim3 grid(N_OUT / BN, M_ROWS / BM);   // (8, 128)
    gemm_kernel<<<grid, 128, SMEM_TOTAL>>>((float*)d_out);
}

// round 10
// speedup vs baseline: 1.7440x; 1.0289x over previous
#include <cuda_runtime.h>
#include <cuda_bf16.h>
#include <cstdint>

// Problem constants
#define M_ROWS 16384      // 8 * 2048
#define D_IN   512
#define NB     8
#define KTOT   4608       // 512 (relu base) + 512*8 (bs+rbf)
#define N_OUT  512

// GEMM tiling (int8 mma.sync m16n8k32 path)
#define BM 128
#define BN 64
#define BK 64                       // int8 K elements (=bytes) per stage
#define NITER (KTOT / BK)           // 72
#define ASTRIDE 80                  // bytes per smem row: 64B data + 16B pad
#define A_BYTES (BM * ASTRIDE)      // 10240
#define B_BYTES (BN * ASTRIDE)      // 5120
#define STG_BYTES (2 * A_BYTES + 2 * B_BYTES)   // 30720: A1 | A0 | B1 | B0
#define SMEM_TOTAL (2 * STG_BYTES)              // 61440

// Scratch: int8 2-slice fixed-point matrices + per-row scales.
__device__ __align__(16) int8_t g_F1[(size_t)M_ROWS * KTOT];
__device__ __align__(16) int8_t g_F0[(size_t)M_ROWS * KTOT];
__device__ __align__(16) int8_t g_W1[(size_t)N_OUT * KTOT];
__device__ __align__(16) int8_t g_W0[(size_t)N_OUT * KTOT];
__device__ float  g_sF[M_ROWS];
__device__ float  g_sW[N_OUT];

// ---------------------------------------------------------------------------
// PTX helpers — base sm_80-class features, valid on compute_100
// ---------------------------------------------------------------------------
__device__ __forceinline__ uint32_t smem_u32(const void* p) {
    uint32_t a;
    asm("{ .reg .u64 t; cvta.to.shared.u64 t, %1; cvt.u32.u64 %0, t; }" : "=r"(a) : "l"(p));
    return a;
}
__device__ __forceinline__ void cp_async16(uint32_t s, const void* g) {
    asm volatile("cp.async.cg.shared.global [%0], [%1], 16;" :: "r"(s), "l"(g));
}
#define CP_COMMIT() asm volatile("cp.async.commit_group;" ::: "memory")
#define CP_WAIT(n)  asm volatile("cp.async.wait_group %0;" :: "n"(n) : "memory")

__device__ __forceinline__ void ldsm4(uint32_t* r, uint32_t addr) {
    asm volatile("ldmatrix.sync.aligned.m8n8.x4.shared.b16 {%0,%1,%2,%3}, [%4];"
                 : "=r"(r[0]), "=r"(r[1]), "=r"(r[2]), "=r"(r[3]) : "r"(addr));
}
// s8 mma m16n8k32, s32 accumulate
__device__ __forceinline__ void imma16832(int* c, const uint32_t* a,
                                          uint32_t b0, uint32_t b1) {
    asm volatile("mma.sync.aligned.m16n8k32.row.col.s32.s8.s8.s32 "
                 "{%0,%1,%2,%3}, {%4,%5,%6,%7}, {%8,%9}, {%0,%1,%2,%3};"
                 : "+r"(c[0]), "+r"(c[1]), "+r"(c[2]), "+r"(c[3])
                 : "r"(a[0]), "r"(a[1]), "r"(a[2]), "r"(a[3]), "r"(b0), "r"(b1));
}

// 2-slice int8 quantization: q in [-16256, 16256] -> h in [-127,127], l in [-64,64]
__device__ __forceinline__ void quant2(float q, int& h, int& l) {
    h = __float2int_rn(q * 0.0078125f);          // q/128
    l = __float2int_rn(q - 128.0f * (float)h);
}

// ---------------------------------------------------------------------------
// Kernel 0: quantize weights to 2-slice int8, per-output-row scale
// ---------------------------------------------------------------------------
__global__ void prep_kernel(const float* __restrict__ bw,
                            const float* __restrict__ sw) {
    int o = blockIdx.x;           // 0..511
    int t = threadIdx.x;          // 256 threads
    size_t rb = (size_t)o * KTOT;
    const float* sp = sw + (size_t)o * (D_IN * NB);

    // Pass 1: row max |W|
    float m = 0.0f;
    for (int k = t; k < D_IN; k += 256) m = fmaxf(m, fabsf(bw[o * D_IN + k]));
    for (int k = t; k < D_IN * NB; k += 256) m = fmaxf(m, fabsf(sp[k]));
    #pragma unroll
    for (int off = 16; off; off >>= 1)
        m = fmaxf(m, __shfl_xor_sync(0xFFFFFFFFu, m, off));
    __shared__ float red[8];
    __shared__ float s_inv;
    if ((t & 31) == 0) red[t >> 5] = m;
    __syncthreads();
    if (t == 0) {
        float mx = 0.0f;
        #pragma unroll
        for (int i = 0; i < 8; i++) mx = fmaxf(mx, red[i]);
        float sW = fmaxf(mx, 1e-20f) * (1.0f / 16256.0f);
        g_sW[o] = sW;
        s_inv = 1.0f / sW;
    }
    __syncthreads();
    const float inv = s_inv;

    // Pass 2: quantize
    for (int k = t; k < D_IN; k += 256) {
        int h, l; quant2(bw[o * D_IN + k] * inv, h, l);
        g_W1[rb + k] = (int8_t)h; g_W0[rb + k] = (int8_t)l;
    }
    for (int k = t; k < D_IN * NB; k += 256) {
        int h, l; quant2(sp[k] * inv, h, l);
        g_W1[rb + D_IN + k] = (int8_t)h; g_W0[rb + D_IN + k] = (int8_t)l;
    }
}

// ---------------------------------------------------------------------------
// Kernel 1: layernorm + features -> 2-slice int8 with per-row scale
// ---------------------------------------------------------------------------
__global__ void feat_kernel(const float* __restrict__ x,
                            const float* __restrict__ gamma,
                            const float* __restrict__ beta) {
    const int row = blockIdx.x;
    const int t   = threadIdx.x;        // 256 threads, 2 dims each
    const float* xr = x + (size_t)row * D_IN;

    float v0 = xr[t];
    float v1 = xr[t + 256];
    float s  = v0 + v1;
    float s2 = v0 * v0 + v1 * v1;
    #pragma unroll
    for (int off = 16; off; off >>= 1) {
        s  += __shfl_xor_sync(0xFFFFFFFFu, s,  off);
        s2 += __shfl_xor_sync(0xFFFFFFFFu, s2, off);
    }
    __shared__ float red[16];
    __shared__ float mu_s, rstd_s, sinv_s;
    int wid = t >> 5, lane = t & 31;
    if (lane == 0) { red[wid] = s; red[8 + wid] = s2; }
    __syncthreads();
    if (t == 0) {
        float ts = 0.f, ts2 = 0.f;
        #pragma unroll
        for (int i = 0; i < 8; i++) { ts += red[i]; ts2 += red[8 + i]; }
        float mu  = ts * (1.0f / 512.0f);
        float var = ts2 * (1.0f / 512.0f) - mu * mu;
        mu_s   = mu;
        rstd_s = rsqrtf(var + 1e-5f);
    }
    __syncthreads();
    const float mu = mu_s, rstd = rstd_s;

    const float H    = 3.0f / 5.0f;
    const float INVD = 7.0f / 3.0f;

    // Compute all 18 features of this thread's 2 dims, track local max
    float fr[2];         // relu
    float fs[2][8];      // bspline + rbf
    float lmax = 0.0f;

    #pragma unroll
    for (int half = 0; half < 2; half++) {
        const int   d  = t + half * 256;
        const float xv = half ? v1 : v0;
        const float xn = (xv - mu) * rstd * gamma[d] + beta[d];

        fr[half] = fmaxf(xn, 0.0f);
        lmax = fmaxf(lmax, fr[half]);

        // Cox-de Boor, uniform knots t_i = (i-3)*H - 1.5, i=0..11
        float b[11];
        #pragma unroll
        for (int i = 0; i < 11; i++) {
            float t0 = (float)(i - 3) * H - 1.5f;
            float t1 = (float)(i - 2) * H - 1.5f;
            b[i] = (xn >= t0 && xn < t1) ? 1.0f : 0.0f;
        }
        #pragma unroll
        for (int k = 1; k <= 3; k++) {
            const float inv = 1.0f / ((float)k * H);
            #pragma unroll
            for (int i = 0; i + k < 11; i++) {
                float ti   = (float)(i - 3) * H - 1.5f;
                float tik1 = (float)(i + k - 2) * H - 1.5f;
                float left  = (xn - ti) * inv;
                float right = (tik1 - xn) * inv;
                b[i] = left * b[i] + right * b[i + 1];
            }
        }
        #pragma unroll
        for (int j = 0; j < 8; j++) {
            float g = -1.5f + (float)j * (3.0f / 7.0f);
            float u = (xn - g) * INVD;
            float f = b[j] + __expf(-u * u);
            fs[half][j] = f;
            lmax = fmaxf(lmax, f);
        }
    }

    // Block max -> per-row scale
    #pragma unroll
    for (int off = 16; off; off >>= 1)
        lmax = fmaxf(lmax, __shfl_xor_sync(0xFFFFFFFFu, lmax, off));
    if (lane == 0) red[wid] = lmax;
    __syncthreads();
    if (t == 0) {
        float mx = 0.0f;
        #pragma unroll
        for (int i = 0; i < 8; i++) mx = fmaxf(mx, red[i]);
        float sF = fmaxf(mx, 1e-20f) * (1.0f / 16256.0f);
        g_sF[row] = sF;
        sinv_s = 1.0f / sF;
    }
    __syncthreads();
    const float inv = sinv_s;

    size_t rb = (size_t)row * KTOT;
    #pragma unroll
    for (int half = 0; half < 2; half++) {
        const int d = t + half * 256;
        int h, l;
        quant2(fr[half] * inv, h, l);
        g_F1[rb + d] = (int8_t)h;
        g_F0[rb + d] = (int8_t)l;

        uint32_t h_lo = 0, h_hi = 0, l_lo = 0, l_hi = 0;
        #pragma unroll
        for (int j = 0; j < 4; j++) {
            int hh, ll;
            quant2(fs[half][j] * inv, hh, ll);
            h_lo |= (uint32_t)(uint8_t)(int8_t)hh << (8 * j);
            l_lo |= (uint32_t)(uint8_t)(int8_t)ll << (8 * j);
            quant2(fs[half][j + 4] * inv, hh, ll);
            h_hi |= (uint32_t)(uint8_t)(int8_t)hh << (8 * j);
            l_hi |= (uint32_t)(uint8_t)(int8_t)ll << (8 * j);
        }
        *(uint2*)(g_F1 + rb + D_IN + (size_t)d * NB) = make_uint2(h_lo, h_hi);
        *(uint2*)(g_F0 + rb + D_IN + (size_t)d * NB) = make_uint2(l_lo, l_hi);
    }
}

// ---------------------------------------------------------------------------
// Dummy kernel: shifts ncu's -s 5 capture slot onto the GEMM launch.
// ---------------------------------------------------------------------------
__global__ void align_kernel() {}

// ---------------------------------------------------------------------------
// Kernel 2: int8 m16n8k32 GEMM, 2-slice compensation
//   C = sF*sW * (16384*F1W1 + 128*(F1W0 + F0W1))   [F0W0 dropped]
// CTA: 128(M) x 64(N), 8 warps (4m x 2n), warp tile 32x32.
// 2-stage cp.async pipeline, 2 CTAs/SM -> 4 warps/SMSP for issue hiding.
// ---------------------------------------------------------------------------
__global__ __launch_bounds__(256, 2) void gemm_kernel(float* __restrict__ C) {
    extern __shared__ char smem[];
    const uint32_t sbase = smem_u32(smem);
    const int t    = threadIdx.x;
    const int wid  = t >> 5;
    const int wm   = wid & 3;           // m sub-tile (0..3), 32 rows
    const int wn   = wid >> 2;          // n sub-tile (0..1), 32 cols
    const int lane = t & 31;
    const int m0   = blockIdx.y * BM;
    const int n0   = blockIdx.x * BN;

    const int8_t* A1_g = g_F1 + (size_t)m0 * KTOT;
    const int8_t* A0_g = g_F0 + (size_t)m0 * KTOT;
    const int8_t* B1_g = g_W1 + (size_t)n0 * KTOT;
    const int8_t* B0_g = g_W0 + (size_t)n0 * KTOT;

    // Per-lane ldmatrix base offsets
    const uint32_t a_off = (uint32_t)((((lane >> 3) & 1) * 8 + (lane & 7)) * ASTRIDE
                                      + (lane >> 4) * 16);
    const uint32_t b_off = (uint32_t)((((lane >> 4) & 1) * 8 + (lane & 7)) * ASTRIDE
                                      + ((lane >> 3) & 1) * 16);

    int accA[2][4][4];   // F1*W1
    int accB[2][4][4];   // F1*W0 + F0*W1
    #pragma unroll
    for (int i = 0; i < 2; i++)
        #pragma unroll
        for (int j = 0; j < 4; j++)
            #pragma unroll
            for (int q = 0; q < 4; q++) { accA[i][j][q] = 0; accB[i][j][q] = 0; }

    // ---- stage loader: 6 cp.async of 16B per thread (256 threads) ----
    auto load_stage = [&](int st, int kc) {
        const uint32_t stage = sbase + st * STG_BYTES;
        #pragma unroll
        for (int r = 0; r < 2; r++) {
            int u = t + r * 256;               // 0..511  (A: 128 rows x 4 chunks)
            int row = u >> 2, ch = u & 3;
            size_t go = (size_t)row * KTOT + kc + ch * 16;
            uint32_t so = (uint32_t)(row * ASTRIDE + ch * 16);
            cp_async16(stage + so,            A1_g + go);
            cp_async16(stage + A_BYTES + so,  A0_g + go);
        }
        {
            int u = t;                         // 0..255  (B: 64 rows x 4 chunks)
            int row = u >> 2, ch = u & 3;
            size_t go = (size_t)row * KTOT + kc + ch * 16;
            uint32_t so = (uint32_t)(row * ASTRIDE + ch * 16);
            cp_async16(stage + 2 * A_BYTES + so,            B1_g + go);
            cp_async16(stage + 2 * A_BYTES + B_BYTES + so,  B0_g + go);
        }
    };

    load_stage(0, 0);
    CP_COMMIT();

    for (int i = 0; i < NITER; i++) {
        if (i + 1 < NITER) {
            load_stage((i + 1) & 1, (i + 1) * BK);
            CP_COMMIT();
            CP_WAIT(1);
        } else {
            CP_WAIT(0);
        }
        __syncthreads();

        const uint32_t stage = sbase + (i & 1) * STG_BYTES;
        const uint32_t sA1 = stage;
        const uint32_t sA0 = stage + A_BYTES;
        const uint32_t sB1 = stage + 2 * A_BYTES;
        const uint32_t sB0 = stage + 2 * A_BYTES + B_BYTES;
        const uint32_t awarp = (uint32_t)(wm * 32 * ASTRIDE);
        const uint32_t bwarp = (uint32_t)(wn * 32 * ASTRIDE);

        #pragma unroll
        for (int s = 0; s < 2; s++) {       // two k32 steps
            const uint32_t ks = (uint32_t)(s * 32);   // 32 int8 = 32 bytes
            uint32_t a1[2][4], a0[2][4];
            #pragma unroll
            for (int im = 0; im < 2; im++) {
                ldsm4(a1[im], sA1 + awarp + (uint32_t)(im * 16 * ASTRIDE) + a_off + ks);
                ldsm4(a0[im], sA0 + awarp + (uint32_t)(im * 16 * ASTRIDE) + a_off + ks);
            }
            // B fragments per 16-col group (bounds live registers)
            #pragma unroll
            for (int jj = 0; jj < 2; jj++) {
                uint32_t b1[4], b0[4];
                ldsm4(b1, sB1 + bwarp + (uint32_t)(jj * 16 * ASTRIDE) + b_off + ks);
                ldsm4(b0, sB0 + bwarp + (uint32_t)(jj * 16 * ASTRIDE) + b_off + ks);
                #pragma unroll
                for (int im = 0; im < 2; im++)
                    #pragma unroll
                    for (int jh = 0; jh < 2; jh++) {
                        int j = jj * 2 + jh;
                        uint32_t bh0 = b1[jh * 2], bh1 = b1[jh * 2 + 1];
                        uint32_t bl0 = b0[jh * 2], bl1 = b0[jh * 2 + 1];
                        imma16832(accA[im][j], a1[im], bh0, bh1);   // F1*W1
                        imma16832(accB[im][j], a1[im], bl0, bl1);   // F1*W0
                        imma16832(accB[im][j], a0[im], bh0, bh1);   // F0*W1
                    }
            }
        }
        __syncthreads();   // all warps done with this stage before refill
    }

    // Writeout: C = (16384*accA + 128*accB) * sF[row] * sW[col]
    //   row = m0 + wm*32 + im*16 + lane/4 (+8)
    //   col = n0 + wn*32 + j*8 + (lane%4)*2
    #pragma unroll
    for (int im = 0; im < 2; im++) {
        int r0 = m0 + wm * 32 + im * 16 + (lane >> 2);
        float sf0 = g_sF[r0];
        float sf1 = g_sF[r0 + 8];
        #pragma unroll
        for (int j = 0; j < 4; j++) {
            int cc = n0 + wn * 32 + j * 8 + (lane & 3) * 2;
            float sw0 = g_sW[cc], sw1 = g_sW[cc + 1];
            float v0 = 16384.0f * (float)accA[im][j][0] + 128.0f * (float)accB[im][j][0];
            float v1 = 16384.0f * (float)accA[im][j][1] + 128.0f * (float)accB[im][j][1];
            float v2 = 16384.0f * (float)accA[im][j][2] + 128.0f * (float)accB[im][j][2];
            float v3 = 16384.0f * (float)accA[im][j][3] + 128.0f * (float)accB[im][j][3];
            *(float2*)(C + (size_t)r0 * N_OUT + cc) =
                make_float2(v0 * sf0 * sw0, v1 * sf0 * sw1);
            *(float2*)(C + (size_t)(r0 + 8) * N_OUT + cc) =
                make_float2(v2 * sf1 * sw0, v3 * sf1 * sw1);
        }
    }
}

// ---------------------------------------------------------------------------
extern "C" void kernel_launch(void* const* d_in, const int* in_sizes, int n_in,
                              void* d_out, int out_size) {
    const float* x        = (const float*)d_in[0];
    const float* ln_gamma = (const float*)d_in[1];
    const float* ln_beta  = (const float*)d_in[2];
    const float* base_w   = (const float*)d_in[3];
    const float* spline_w = (const float*)d_in[4];
    (void)in_sizes; (void)n_in; (void)out_size;

    cudaFuncSetAttribute(gemm_kernel, cudaFuncAttributeMaxDynamicSharedMemorySize, SMEM_TOTAL);

    prep_kernel<<<N_OUT, 256>>>(base_w, spline_w);
    feat_kernel<<<M_ROWS, 256>>>(x, ln_gamma, ln_beta);
    align_kernel<<<1, 32>>>();   // shifts ncu -s 5 capture onto the GEMM
    dim3 grid(N_OUT / BN, M_ROWS / BM);   // (8, 128)
    gemm_kernel<<<grid, 256, SMEM_TOTAL>>>((float*)d_out);
}

// round 11
// speedup vs baseline: 1.9448x; 1.1152x over previous
#include <cuda_runtime.h>
#include <cuda_bf16.h>
#include <cstdint>

// Problem constants
#define M_ROWS 16384      // 8 * 2048
#define D_IN   512
#define NB     8
#define KTOT   4608       // 512 (relu base) + 512*8 (bs+rbf)
#define N_OUT  512

// GEMM tiling (int8 mma.sync m16n8k32 path)
#define BM 128
#define BN 64
#define BK 128                      // int8 K elements (=bytes) per stage
#define NITER (KTOT / BK)           // 36
#define ASTRIDE 144                 // bytes per smem row: 128B data + 16B pad
#define A_BYTES (BM * ASTRIDE)      // 18432
#define B_BYTES (BN * ASTRIDE)      // 9216
#define STG_BYTES (2 * A_BYTES + 2 * B_BYTES)   // 55296: A1 | A0 | B1 | B0
#define SMEM_TOTAL (2 * STG_BYTES)              // 110592 (2 CTAs/SM = 216KB)

// Scratch: int8 2-slice fixed-point matrices + per-row scales.
__device__ __align__(16) int8_t g_F1[(size_t)M_ROWS * KTOT];
__device__ __align__(16) int8_t g_F0[(size_t)M_ROWS * KTOT];
__device__ __align__(16) int8_t g_W1[(size_t)N_OUT * KTOT];
__device__ __align__(16) int8_t g_W0[(size_t)N_OUT * KTOT];
__device__ float  g_sF[M_ROWS];
__device__ float  g_sW[N_OUT];

// ---------------------------------------------------------------------------
// PTX helpers — base sm_80-class features, valid on compute_100
// ---------------------------------------------------------------------------
__device__ __forceinline__ uint32_t smem_u32(const void* p) {
    uint32_t a;
    asm("{ .reg .u64 t; cvta.to.shared.u64 t, %1; cvt.u32.u64 %0, t; }" : "=r"(a) : "l"(p));
    return a;
}
__device__ __forceinline__ void cp_async16(uint32_t s, const void* g) {
    asm volatile("cp.async.cg.shared.global [%0], [%1], 16;" :: "r"(s), "l"(g));
}
#define CP_COMMIT() asm volatile("cp.async.commit_group;" ::: "memory")
#define CP_WAIT(n)  asm volatile("cp.async.wait_group %0;" :: "n"(n) : "memory")

__device__ __forceinline__ void ldsm4(uint32_t* r, uint32_t addr) {
    asm volatile("ldmatrix.sync.aligned.m8n8.x4.shared.b16 {%0,%1,%2,%3}, [%4];"
                 : "=r"(r[0]), "=r"(r[1]), "=r"(r[2]), "=r"(r[3]) : "r"(addr));
}
// s8 mma m16n8k32, s32 accumulate
__device__ __forceinline__ void imma16832(int* c, const uint32_t* a,
                                          uint32_t b0, uint32_t b1) {
    asm volatile("mma.sync.aligned.m16n8k32.row.col.s32.s8.s8.s32 "
                 "{%0,%1,%2,%3}, {%4,%5,%6,%7}, {%8,%9}, {%0,%1,%2,%3};"
                 : "+r"(c[0]), "+r"(c[1]), "+r"(c[2]), "+r"(c[3])
                 : "r"(a[0]), "r"(a[1]), "r"(a[2]), "r"(a[3]), "r"(b0), "r"(b1));
}

// 2-slice int8 quantization: q in [-16256, 16256] -> h in [-127,127], l in [-64,64]
__device__ __forceinline__ void quant2(float q, int& h, int& l) {
    h = __float2int_rn(q * 0.0078125f);          // q/128
    l = __float2int_rn(q - 128.0f * (float)h);
}

// ---------------------------------------------------------------------------
// Kernel 0: quantize weights to 2-slice int8, per-output-row scale
// ---------------------------------------------------------------------------
__global__ void prep_kernel(const float* __restrict__ bw,
                            const float* __restrict__ sw) {
    int o = blockIdx.x;           // 0..511
    int t = threadIdx.x;          // 256 threads
    size_t rb = (size_t)o * KTOT;
    const float* sp = sw + (size_t)o * (D_IN * NB);

    // Pass 1: row max |W|
    float m = 0.0f;
    for (int k = t; k < D_IN; k += 256) m = fmaxf(m, fabsf(bw[o * D_IN + k]));
    for (int k = t; k < D_IN * NB; k += 256) m = fmaxf(m, fabsf(sp[k]));
    #pragma unroll
    for (int off = 16; off; off >>= 1)
        m = fmaxf(m, __shfl_xor_sync(0xFFFFFFFFu, m, off));
    __shared__ float red[8];
    __shared__ float s_inv;
    if ((t & 31) == 0) red[t >> 5] = m;
    __syncthreads();
    if (t == 0) {
        float mx = 0.0f;
        #pragma unroll
        for (int i = 0; i < 8; i++) mx = fmaxf(mx, red[i]);
        float sW = fmaxf(mx, 1e-20f) * (1.0f / 16256.0f);
        g_sW[o] = sW;
        s_inv = 1.0f / sW;
    }
    __syncthreads();
    const float inv = s_inv;

    // Pass 2: quantize
    for (int k = t; k < D_IN; k += 256) {
        int h, l; quant2(bw[o * D_IN + k] * inv, h, l);
        g_W1[rb + k] = (int8_t)h; g_W0[rb + k] = (int8_t)l;
    }
    for (int k = t; k < D_IN * NB; k += 256) {
        int h, l; quant2(sp[k] * inv, h, l);
        g_W1[rb + D_IN + k] = (int8_t)h; g_W0[rb + D_IN + k] = (int8_t)l;
    }
}

// ---------------------------------------------------------------------------
// Kernel 1: layernorm + features -> 2-slice int8 with per-row scale
// ---------------------------------------------------------------------------
__global__ void feat_kernel(const float* __restrict__ x,
                            const float* __restrict__ gamma,
                            const float* __restrict__ beta) {
    const int row = blockIdx.x;
    const int t   = threadIdx.x;        // 256 threads, 2 dims each
    const float* xr = x + (size_t)row * D_IN;

    float v0 = xr[t];
    float v1 = xr[t + 256];
    float s  = v0 + v1;
    float s2 = v0 * v0 + v1 * v1;
    #pragma unroll
    for (int off = 16; off; off >>= 1) {
        s  += __shfl_xor_sync(0xFFFFFFFFu, s,  off);
        s2 += __shfl_xor_sync(0xFFFFFFFFu, s2, off);
    }
    __shared__ float red[16];
    __shared__ float mu_s, rstd_s, sinv_s;
    int wid = t >> 5, lane = t & 31;
    if (lane == 0) { red[wid] = s; red[8 + wid] = s2; }
    __syncthreads();
    if (t == 0) {
        float ts = 0.f, ts2 = 0.f;
        #pragma unroll
        for (int i = 0; i < 8; i++) { ts += red[i]; ts2 += red[8 + i]; }
        float mu  = ts * (1.0f / 512.0f);
        float var = ts2 * (1.0f / 512.0f) - mu * mu;
        mu_s   = mu;
        rstd_s = rsqrtf(var + 1e-5f);
    }
    __syncthreads();
    const float mu = mu_s, rstd = rstd_s;

    const float H    = 3.0f / 5.0f;
    const float INVD = 7.0f / 3.0f;

    // Compute all 18 features of this thread's 2 dims, track local max
    float fr[2];         // relu
    float fs[2][8];      // bspline + rbf
    float lmax = 0.0f;

    #pragma unroll
    for (int half = 0; half < 2; half++) {
        const int   d  = t + half * 256;
        const float xv = half ? v1 : v0;
        const float xn = (xv - mu) * rstd * gamma[d] + beta[d];

        fr[half] = fmaxf(xn, 0.0f);
        lmax = fmaxf(lmax, fr[half]);

        // Cox-de Boor, uniform knots t_i = (i-3)*H - 1.5, i=0..11
        float b[11];
        #pragma unroll
        for (int i = 0; i < 11; i++) {
            float t0 = (float)(i - 3) * H - 1.5f;
            float t1 = (float)(i - 2) * H - 1.5f;
            b[i] = (xn >= t0 && xn < t1) ? 1.0f : 0.0f;
        }
        #pragma unroll
        for (int k = 1; k <= 3; k++) {
            const float inv = 1.0f / ((float)k * H);
            #pragma unroll
            for (int i = 0; i + k < 11; i++) {
                float ti   = (float)(i - 3) * H - 1.5f;
                float tik1 = (float)(i + k - 2) * H - 1.5f;
                float left  = (xn - ti) * inv;
                float right = (tik1 - xn) * inv;
                b[i] = left * b[i] + right * b[i + 1];
            }
        }
        #pragma unroll
        for (int j = 0; j < 8; j++) {
            float g = -1.5f + (float)j * (3.0f / 7.0f);
            float u = (xn - g) * INVD;
            float f = b[j] + __expf(-u * u);
            fs[half][j] = f;
            lmax = fmaxf(lmax, f);
        }
    }

    // Block max -> per-row scale
    #pragma unroll
    for (int off = 16; off; off >>= 1)
        lmax = fmaxf(lmax, __shfl_xor_sync(0xFFFFFFFFu, lmax, off));
    if (lane == 0) red[wid] = lmax;
    __syncthreads();
    if (t == 0) {
        float mx = 0.0f;
        #pragma unroll
        for (int i = 0; i < 8; i++) mx = fmaxf(mx, red[i]);
        float sF = fmaxf(mx, 1e-20f) * (1.0f / 16256.0f);
        g_sF[row] = sF;
        sinv_s = 1.0f / sF;
    }
    __syncthreads();
    const float inv = sinv_s;

    size_t rb = (size_t)row * KTOT;
    #pragma unroll
    for (int half = 0; half < 2; half++) {
        const int d = t + half * 256;
        int h, l;
        quant2(fr[half] * inv, h, l);
        g_F1[rb + d] = (int8_t)h;
        g_F0[rb + d] = (int8_t)l;

        uint32_t h_lo = 0, h_hi = 0, l_lo = 0, l_hi = 0;
        #pragma unroll
        for (int j = 0; j < 4; j++) {
            int hh, ll;
            quant2(fs[half][j] * inv, hh, ll);
            h_lo |= (uint32_t)(uint8_t)(int8_t)hh << (8 * j);
            l_lo |= (uint32_t)(uint8_t)(int8_t)ll << (8 * j);
            quant2(fs[half][j + 4] * inv, hh, ll);
            h_hi |= (uint32_t)(uint8_t)(int8_t)hh << (8 * j);
            l_hi |= (uint32_t)(uint8_t)(int8_t)ll << (8 * j);
        }
        *(uint2*)(g_F1 + rb + D_IN + (size_t)d * NB) = make_uint2(h_lo, h_hi);
        *(uint2*)(g_F0 + rb + D_IN + (size_t)d * NB) = make_uint2(l_lo, l_hi);
    }
}

// ---------------------------------------------------------------------------
// Dummy kernel: keeps ncu's -s 5 capture slot on the GEMM launch.
// ---------------------------------------------------------------------------
__global__ void align_kernel() {}

// ---------------------------------------------------------------------------
// Kernel 2: int8 m16n8k32 GEMM, 2-slice compensation
//   C = sF*sW * (16384*F1W1 + 128*(F1W0 + F0W1))   [F0W0 dropped]
// CTA: 128(M) x 64(N), 8 warps (4m x 2n), warp tile 32x32.
// BK=128 stages (36 iters): 4x fewer barriers than BK=64/72-iter config.
// 2-stage cp.async pipeline, 2 CTAs/SM.
// ---------------------------------------------------------------------------
__global__ __launch_bounds__(256, 2) void gemm_kernel(float* __restrict__ C) {
    extern __shared__ char smem[];
    const uint32_t sbase = smem_u32(smem);
    const int t    = threadIdx.x;
    const int wid  = t >> 5;
    const int wm   = wid & 3;           // m sub-tile (0..3), 32 rows
    const int wn   = wid >> 2;          // n sub-tile (0..1), 32 cols
    const int lane = t & 31;
    const int m0   = blockIdx.y * BM;
    const int n0   = blockIdx.x * BN;

    const int8_t* A1_g = g_F1 + (size_t)m0 * KTOT;
    const int8_t* A0_g = g_F0 + (size_t)m0 * KTOT;
    const int8_t* B1_g = g_W1 + (size_t)n0 * KTOT;
    const int8_t* B0_g = g_W0 + (size_t)n0 * KTOT;

    // Per-lane ldmatrix base offsets
    const uint32_t a_off = (uint32_t)((((lane >> 3) & 1) * 8 + (lane & 7)) * ASTRIDE
                                      + (lane >> 4) * 16);
    const uint32_t b_off = (uint32_t)((((lane >> 4) & 1) * 8 + (lane & 7)) * ASTRIDE
                                      + ((lane >> 3) & 1) * 16);

    int accA[2][4][4];   // F1*W1
    int accB[2][4][4];   // F1*W0 + F0*W1
    #pragma unroll
    for (int i = 0; i < 2; i++)
        #pragma unroll
        for (int j = 0; j < 4; j++)
            #pragma unroll
            for (int q = 0; q < 4; q++) { accA[i][j][q] = 0; accB[i][j][q] = 0; }

    // ---- stage loader: 12 cp.async of 16B per thread (256 threads) ----
    // A: 128 rows x 8 chunks = 1024 units per matrix; B: 64 x 8 = 512.
    auto load_stage = [&](int st, int kc) {
        const uint32_t stage = sbase + st * STG_BYTES;
        #pragma unroll
        for (int r = 0; r < 4; r++) {
            int u = t + r * 256;               // 0..1023
            int row = u >> 3, ch = u & 7;
            size_t go = (size_t)row * KTOT + kc + ch * 16;
            uint32_t so = (uint32_t)(row * ASTRIDE + ch * 16);
            cp_async16(stage + so,            A1_g + go);
            cp_async16(stage + A_BYTES + so,  A0_g + go);
        }
        #pragma unroll
        for (int r = 0; r < 2; r++) {
            int u = t + r * 256;               // 0..511
            int row = u >> 3, ch = u & 7;
            size_t go = (size_t)row * KTOT + kc + ch * 16;
            uint32_t so = (uint32_t)(row * ASTRIDE + ch * 16);
            cp_async16(stage + 2 * A_BYTES + so,            B1_g + go);
            cp_async16(stage + 2 * A_BYTES + B_BYTES + so,  B0_g + go);
        }
    };

    load_stage(0, 0);
    CP_COMMIT();

    for (int i = 0; i < NITER; i++) {
        if (i + 1 < NITER) {
            load_stage((i + 1) & 1, (i + 1) * BK);
            CP_COMMIT();
            CP_WAIT(1);
        } else {
            CP_WAIT(0);
        }
        __syncthreads();

        const uint32_t stage = sbase + (i & 1) * STG_BYTES;
        const uint32_t sA1 = stage;
        const uint32_t sA0 = stage + A_BYTES;
        const uint32_t sB1 = stage + 2 * A_BYTES;
        const uint32_t sB0 = stage + 2 * A_BYTES + B_BYTES;
        const uint32_t awarp = (uint32_t)(wm * 32 * ASTRIDE);
        const uint32_t bwarp = (uint32_t)(wn * 32 * ASTRIDE);

        #pragma unroll
        for (int s = 0; s < 4; s++) {       // four k32 steps
            const uint32_t ks = (uint32_t)(s * 32);   // 32 int8 = 32 bytes
            uint32_t a1[2][4], a0[2][4];
            #pragma unroll
            for (int im = 0; im < 2; im++) {
                ldsm4(a1[im], sA1 + awarp + (uint32_t)(im * 16 * ASTRIDE) + a_off + ks);
                ldsm4(a0[im], sA0 + awarp + (uint32_t)(im * 16 * ASTRIDE) + a_off + ks);
            }
            // B fragments per 16-col group (bounds live registers)
            #pragma unroll
            for (int jj = 0; jj < 2; jj++) {
                uint32_t b1[4], b0[4];
                ldsm4(b1, sB1 + bwarp + (uint32_t)(jj * 16 * ASTRIDE) + b_off + ks);
                ldsm4(b0, sB0 + bwarp + (uint32_t)(jj * 16 * ASTRIDE) + b_off + ks);
                #pragma unroll
                for (int im = 0; im < 2; im++)
                    #pragma unroll
                    for (int jh = 0; jh < 2; jh++) {
                        int j = jj * 2 + jh;
                        uint32_t bh0 = b1[jh * 2], bh1 = b1[jh * 2 + 1];
                        uint32_t bl0 = b0[jh * 2], bl1 = b0[jh * 2 + 1];
                        imma16832(accA[im][j], a1[im], bh0, bh1);   // F1*W1
                        imma16832(accB[im][j], a1[im], bl0, bl1);   // F1*W0
                        imma16832(accB[im][j], a0[im], bh0, bh1);   // F0*W1
                    }
            }
        }
        __syncthreads();   // all warps done with this stage before refill
    }

    // Writeout: C = (16384*accA + 128*accB) * sF[row] * sW[col]
    #pragma unroll
    for (int im = 0; im < 2; im++) {
        int r0 = m0 + wm * 32 + im * 16 + (lane >> 2);
        float sf0 = g_sF[r0];
        float sf1 = g_sF[r0 + 8];
        #pragma unroll
        for (int j = 0; j < 4; j++) {
            int cc = n0 + wn * 32 + j * 8 + (lane & 3) * 2;
            float sw0 = g_sW[cc], sw1 = g_sW[cc + 1];
            float v0 = 16384.0f * (float)accA[im][j][0] + 128.0f * (float)accB[im][j][0];
            float v1 = 16384.0f * (float)accA[im][j][1] + 128.0f * (float)accB[im][j][1];
            float v2 = 16384.0f * (float)accA[im][j][2] + 128.0f * (float)accB[im][j][2];
            float v3 = 16384.0f * (float)accA[im][j][3] + 128.0f * (float)accB[im][j][3];
            *(float2*)(C + (size_t)r0 * N_OUT + cc) =
                make_float2(v0 * sf0 * sw0, v1 * sf0 * sw1);
            *(float2*)(C + (size_t)(r0 + 8) * N_OUT + cc) =
                make_float2(v2 * sf1 * sw0, v3 * sf1 * sw1);
        }
    }
}

// ---------------------------------------------------------------------------
extern "C" void kernel_launch(void* const* d_in, const int* in_sizes, int n_in,
                              void* d_out, int out_size) {
    const float* x        = (const float*)d_in[0];
    const float* ln_gamma = (const float*)d_in[1];
    const float* ln_beta  = (const float*)d_in[2];
    const float* base_w   = (const float*)d_in[3];
    const float* spline_w = (const float*)d_in[4];
    (void)in_sizes; (void)n_in; (void)out_size;

    cudaFuncSetAttribute(gemm_kernel, cudaFuncAttributeMaxDynamicSharedMemorySize, SMEM_TOTAL);

    prep_kernel<<<N_OUT, 256>>>(base_w, spline_w);
    feat_kernel<<<M_ROWS, 256>>>(x, ln_gamma, ln_beta);
    align_kernel<<<1, 32>>>();   // keeps ncu -s 5 capture on the GEMM
    dim3 grid(N_OUT / BN, M_ROWS / BM);   // (8, 128)
    gemm_kernel<<<grid, 256, SMEM_TOTAL>>>((float*)d_out);
}

// round 13
// speedup vs baseline: 2.3944x; 1.2312x over previous
#include <cuda_runtime.h>
#include <cuda_fp16.h>
#include <cstdint>

// Problem constants
#define M_ROWS 16384      // 8 * 2048
#define D_IN   512
#define NB     8
#define KTOT   4608       // 512 (relu base) + 512*8 (bs+rbf)
#define N_OUT  512

// GEMM tiling (fp16 mma.sync m16n8k16, fp32 accum — single slice)
#define BM 128
#define BN 64
#define BK 128                      // fp16 K elements per stage (256 B/row)
#define NITER (KTOT / BK)           // 36
#define ASTRIDE 272                 // bytes per smem row: 256B data + 16B pad
#define A_BYTES (BM * ASTRIDE)      // 34816
#define B_BYTES (BN * ASTRIDE)      // 17408
#define STG_BYTES (A_BYTES + B_BYTES)           // 52224: A | B
#define SMEM_TOTAL (2 * STG_BYTES)              // 104448 (2 CTAs/SM = 204KB)

// Scratch: fp16 feature + weight matrices
__device__ __align__(16) __half g_F[(size_t)M_ROWS * KTOT];
__device__ __align__(16) __half g_W[(size_t)N_OUT * KTOT];

// ---------------------------------------------------------------------------
// PTX helpers — base sm_80-class features, valid on compute_100
// ---------------------------------------------------------------------------
__device__ __forceinline__ uint32_t smem_u32(const void* p) {
    uint32_t a;
    asm("{ .reg .u64 t; cvta.to.shared.u64 t, %1; cvt.u32.u64 %0, t; }" : "=r"(a) : "l"(p));
    return a;
}
__device__ __forceinline__ void cp_async16(uint32_t s, const void* g) {
    asm volatile("cp.async.cg.shared.global [%0], [%1], 16;" :: "r"(s), "l"(g));
}
#define CP_COMMIT() asm volatile("cp.async.commit_group;" ::: "memory")
#define CP_WAIT(n)  asm volatile("cp.async.wait_group %0;" :: "n"(n) : "memory")

__device__ __forceinline__ void ldsm4(uint32_t* r, uint32_t addr) {
    asm volatile("ldmatrix.sync.aligned.m8n8.x4.shared.b16 {%0,%1,%2,%3}, [%4];"
                 : "=r"(r[0]), "=r"(r[1]), "=r"(r[2]), "=r"(r[3]) : "r"(addr));
}
// fp16 mma m16n8k16, fp32 accumulate
__device__ __forceinline__ void hmma16816(float* c, const uint32_t* a,
                                          uint32_t b0, uint32_t b1) {
    asm volatile("mma.sync.aligned.m16n8k16.row.col.f32.f16.f16.f32 "
                 "{%0,%1,%2,%3}, {%4,%5,%6,%7}, {%8,%9}, {%0,%1,%2,%3};"
                 : "+f"(c[0]), "+f"(c[1]), "+f"(c[2]), "+f"(c[3])
                 : "r"(a[0]), "r"(a[1]), "r"(a[2]), "r"(a[3]), "r"(b0), "r"(b1));
}

// ---------------------------------------------------------------------------
// Kernel 0: convert weights to fp16, concat [base | spline]
// ---------------------------------------------------------------------------
__global__ void prep_kernel(const float* __restrict__ bw,
                            const float* __restrict__ sw) {
    int o = blockIdx.x;           // 0..511
    int t = threadIdx.x;          // 256 threads
    size_t rb = (size_t)o * KTOT;
    for (int k = t; k < D_IN; k += 256)
        g_W[rb + k] = __float2half(bw[o * D_IN + k]);
    const float* sp = sw + (size_t)o * (D_IN * NB);
    for (int k = t; k < D_IN * NB; k += 256)
        g_W[rb + D_IN + k] = __float2half(sp[k]);
}

// ---------------------------------------------------------------------------
// Kernel 1: layernorm + features -> fp16
// ---------------------------------------------------------------------------
__global__ void feat_kernel(const float* __restrict__ x,
                            const float* __restrict__ gamma,
                            const float* __restrict__ beta) {
    const int row = blockIdx.x;
    const int t   = threadIdx.x;        // 256 threads, 2 dims each
    const float* xr = x + (size_t)row * D_IN;

    float v0 = xr[t];
    float v1 = xr[t + 256];
    float s  = v0 + v1;
    float s2 = v0 * v0 + v1 * v1;
    #pragma unroll
    for (int off = 16; off; off >>= 1) {
        s  += __shfl_xor_sync(0xFFFFFFFFu, s,  off);
        s2 += __shfl_xor_sync(0xFFFFFFFFu, s2, off);
    }
    __shared__ float red[16];
    __shared__ float mu_s, rstd_s;
    int wid = t >> 5, lane = t & 31;
    if (lane == 0) { red[wid] = s; red[8 + wid] = s2; }
    __syncthreads();
    if (t == 0) {
        float ts = 0.f, ts2 = 0.f;
        #pragma unroll
        for (int i = 0; i < 8; i++) { ts += red[i]; ts2 += red[8 + i]; }
        float mu  = ts * (1.0f / 512.0f);
        float var = ts2 * (1.0f / 512.0f) - mu * mu;
        mu_s   = mu;
        rstd_s = rsqrtf(var + 1e-5f);
    }
    __syncthreads();
    const float mu = mu_s, rstd = rstd_s;

    size_t rb = (size_t)row * KTOT;
    const float H    = 3.0f / 5.0f;
    const float INVD = 7.0f / 3.0f;

    #pragma unroll
    for (int half = 0; half < 2; half++) {
        const int   d  = t + half * 256;
        const float xv = half ? v1 : v0;
        const float xn = (xv - mu) * rstd * gamma[d] + beta[d];

        g_F[rb + d] = __float2half(fmaxf(xn, 0.0f));

        // Cox-de Boor, uniform knots t_i = (i-3)*H - 1.5, i=0..11
        float b[11];
        #pragma unroll
        for (int i = 0; i < 11; i++) {
            float t0 = (float)(i - 3) * H - 1.5f;
            float t1 = (float)(i - 2) * H - 1.5f;
            b[i] = (xn >= t0 && xn < t1) ? 1.0f : 0.0f;
        }
        #pragma unroll
        for (int k = 1; k <= 3; k++) {
            const float inv = 1.0f / ((float)k * H);
            #pragma unroll
            for (int i = 0; i + k < 11; i++) {
                float ti   = (float)(i - 3) * H - 1.5f;
                float tik1 = (float)(i + k - 2) * H - 1.5f;
                float left  = (xn - ti) * inv;
                float right = (tik1 - xn) * inv;
                b[i] = left * b[i] + right * b[i + 1];
            }
        }

        __half oh[8];
        #pragma unroll
        for (int j = 0; j < 8; j++) {
            float g = -1.5f + (float)j * (3.0f / 7.0f);
            float u = (xn - g) * INVD;
            oh[j] = __float2half(b[j] + __expf(-u * u));
        }
        // 8 halfs = 16B; offset (512 + 8d)*2 bytes is 16B aligned
        *(uint4*)(&g_F[rb + D_IN + (size_t)d * NB]) = *(const uint4*)oh;
    }
}

// ---------------------------------------------------------------------------
// Dummy kernel: keeps ncu's -s 5 capture slot on the GEMM launch.
// ---------------------------------------------------------------------------
__global__ void align_kernel() {}

// ---------------------------------------------------------------------------
// Kernel 2: fp16 m16n8k16 GEMM, fp32 accumulators (single slice)
// CTA: 128(M) x 64(N), 8 warps (4m x 2n), warp tile 32x32.
// BK=128 elements (36 iters), 2-stage cp.async pipeline, 2 CTAs/SM.
// ---------------------------------------------------------------------------
__global__ __launch_bounds__(256, 2) void gemm_kernel(float* __restrict__ C) {
    extern __shared__ char smem[];
    const uint32_t sbase = smem_u32(smem);
    const int t    = threadIdx.x;
    const int wid  = t >> 5;
    const int wm   = wid & 3;           // m sub-tile (0..3), 32 rows
    const int wn   = wid >> 2;          // n sub-tile (0..1), 32 cols
    const int lane = t & 31;
    const int m0   = blockIdx.y * BM;
    const int n0   = blockIdx.x * BN;

    const __half* A_g = g_F + (size_t)m0 * KTOT;
    const __half* B_g = g_W + (size_t)n0 * KTOT;

    // Per-lane ldmatrix base offsets (16-bit k16 fragment maps, proven R5/R6)
    const uint32_t a_off = (uint32_t)((((lane >> 3) & 1) * 8 + (lane & 7)) * ASTRIDE
                                      + (lane >> 4) * 16);
    const uint32_t b_off = (uint32_t)((((lane >> 4) & 1) * 8 + (lane & 7)) * ASTRIDE
                                      + ((lane >> 3) & 1) * 16);

    float acc[2][4][4];
    #pragma unroll
    for (int i = 0; i < 2; i++)
        #pragma unroll
        for (int j = 0; j < 4; j++)
            #pragma unroll
            for (int q = 0; q < 4; q++) acc[i][j][q] = 0.0f;

    // ---- stage loader: 12 cp.async of 16B per thread (256 threads) ----
    // A: 128 rows x 16 chunks = 2048 units; B: 64 x 16 = 1024 units.
    auto load_stage = [&](int st, int kc) {
        const uint32_t stage = sbase + st * STG_BYTES;
        #pragma unroll
        for (int r = 0; r < 8; r++) {
            int u = t + r * 256;               // 0..2047
            int row = u >> 4, ch = u & 15;
            size_t go = (size_t)row * KTOT + kc + ch * 8;   // halfs
            uint32_t so = (uint32_t)(row * ASTRIDE + ch * 16);
            cp_async16(stage + so, A_g + go);
        }
        #pragma unroll
        for (int r = 0; r < 4; r++) {
            int u = t + r * 256;               // 0..1023
            int row = u >> 4, ch = u & 15;
            size_t go = (size_t)row * KTOT + kc + ch * 8;
            uint32_t so = (uint32_t)(row * ASTRIDE + ch * 16);
            cp_async16(stage + A_BYTES + so, B_g + go);
        }
    };

    load_stage(0, 0);
    CP_COMMIT();

    for (int i = 0; i < NITER; i++) {
        if (i + 1 < NITER) {
            load_stage((i + 1) & 1, (i + 1) * BK);
            CP_COMMIT();
            CP_WAIT(1);
        } else {
            CP_WAIT(0);
        }
        __syncthreads();

        const uint32_t stage = sbase + (i & 1) * STG_BYTES;
        const uint32_t sA = stage;
        const uint32_t sB = stage + A_BYTES;
        const uint32_t awarp = (uint32_t)(wm * 32 * ASTRIDE);
        const uint32_t bwarp = (uint32_t)(wn * 32 * ASTRIDE);

        #pragma unroll
        for (int s = 0; s < 8; s++) {       // eight k16 steps
            const uint32_t ks = (uint32_t)(s * 32);   // 16 fp16 = 32 bytes
            uint32_t a[2][4], b[2][4];
            #pragma unroll
            for (int im = 0; im < 2; im++)
                ldsm4(a[im], sA + awarp + (uint32_t)(im * 16 * ASTRIDE) + a_off + ks);
            #pragma unroll
            for (int jj = 0; jj < 2; jj++)
                ldsm4(b[jj], sB + bwarp + (uint32_t)(jj * 16 * ASTRIDE) + b_off + ks);
            #pragma unroll
            for (int im = 0; im < 2; im++)
                #pragma unroll
                for (int jj = 0; jj < 2; jj++)
                    #pragma unroll
                    for (int jh = 0; jh < 2; jh++) {
                        int j = jj * 2 + jh;
                        hmma16816(acc[im][j], a[im],
                                  b[jj][jh * 2], b[jj][jh * 2 + 1]);
                    }
        }
        __syncthreads();   // all warps done with this stage before refill
    }

    // Writeout: row = m0 + wm*32 + im*16 + lane/4 (+8),
    //           col = n0 + wn*32 + j*8 + (lane%4)*2
    #pragma unroll
    for (int im = 0; im < 2; im++) {
        int r0 = m0 + wm * 32 + im * 16 + (lane >> 2);
        #pragma unroll
        for (int j = 0; j < 4; j++) {
            int cc = n0 + wn * 32 + j * 8 + (lane & 3) * 2;
            *(float2*)(C + (size_t)r0 * N_OUT + cc) =
                make_float2(acc[im][j][0], acc[im][j][1]);
            *(float2*)(C + (size_t)(r0 + 8) * N_OUT + cc) =
                make_float2(acc[im][j][2], acc[im][j][3]);
        }
    }
}

// ---------------------------------------------------------------------------
extern "C" void kernel_launch(void* const* d_in, const int* in_sizes, int n_in,
                              void* d_out, int out_size) {
    const float* x        = (const float*)d_in[0];
    const float* ln_gamma = (const float*)d_in[1];
    const float* ln_beta  = (const float*)d_in[2];
    const float* base_w   = (const float*)d_in[3];
    const float* spline_w = (const float*)d_in[4];
    (void)in_sizes; (void)n_in; (void)out_size;

    cudaFuncSetAttribute(gemm_kernel, cudaFuncAttributeMaxDynamicSharedMemorySize, SMEM_TOTAL);

    prep_kernel<<<N_OUT, 256>>>(base_w, spline_w);
    feat_kernel<<<M_ROWS, 256>>>(x, ln_gamma, ln_beta);
    align_kernel<<<1, 32>>>();   // keeps ncu -s 5 capture on the GEMM
    dim3 grid(N_OUT / BN, M_ROWS / BM);   // (8, 128)
    gemm_kernel<<<grid, 256, SMEM_TOTAL>>>((float*)d_out);
}

// round 15
// speedup vs baseline: 2.5557x; 1.0673x over previous
#include <cuda_runtime.h>
#include <cuda_fp16.h>
#include <cstdint>

// Problem constants
#define M_ROWS 16384      // 8 * 2048
#define D_IN   512
#define NB     8
#define KTOT   4608       // 512 (relu base) + 512*8 (bs+rbf)
#define N_OUT  512

// GEMM tiling (fp16 mma.sync m16n8k16, fp32 accum)
#define BM 128
#define BN 128
#define BK 64                       // fp16 K elements per stage (128 B/row)
#define NITER (KTOT / BK)           // 72
#define ASTRIDE 144                 // bytes per smem row: 128B data + 16B pad
#define A_BYTES (BM * ASTRIDE)      // 18432
#define B_BYTES (BN * ASTRIDE)      // 18432
#define STG_BYTES (A_BYTES + B_BYTES)           // 36864: A | B
#define SMEM_TOTAL (2 * STG_BYTES)              // 73728 (2 CTAs/SM = 144KB)

// Scratch: fp16 feature + weight matrices
__device__ __align__(16) __half g_F[(size_t)M_ROWS * KTOT];
__device__ __align__(16) __half g_W[(size_t)N_OUT * KTOT];

// ---------------------------------------------------------------------------
// PTX helpers — base sm_80-class features, valid on compute_100
// ---------------------------------------------------------------------------
__device__ __forceinline__ uint32_t smem_u32(const void* p) {
    uint32_t a;
    asm("{ .reg .u64 t; cvta.to.shared.u64 t, %1; cvt.u32.u64 %0, t; }" : "=r"(a) : "l"(p));
    return a;
}
__device__ __forceinline__ void cp_async16(uint32_t s, const void* g) {
    asm volatile("cp.async.cg.shared.global [%0], [%1], 16;" :: "r"(s), "l"(g));
}
#define CP_COMMIT() asm volatile("cp.async.commit_group;" ::: "memory")
#define CP_WAIT(n)  asm volatile("cp.async.wait_group %0;" :: "n"(n) : "memory")

__device__ __forceinline__ void ldsm4(uint32_t* r, uint32_t addr) {
    asm volatile("ldmatrix.sync.aligned.m8n8.x4.shared.b16 {%0,%1,%2,%3}, [%4];"
                 : "=r"(r[0]), "=r"(r[1]), "=r"(r[2]), "=r"(r[3]) : "r"(addr));
}
// fp16 mma m16n8k16, fp32 accumulate
__device__ __forceinline__ void hmma16816(float* c, const uint32_t* a,
                                          uint32_t b0, uint32_t b1) {
    asm volatile("mma.sync.aligned.m16n8k16.row.col.f32.f16.f16.f32 "
                 "{%0,%1,%2,%3}, {%4,%5,%6,%7}, {%8,%9}, {%0,%1,%2,%3};"
                 : "+f"(c[0]), "+f"(c[1]), "+f"(c[2]), "+f"(c[3])
                 : "r"(a[0]), "r"(a[1]), "r"(a[2]), "r"(a[3]), "r"(b0), "r"(b1));
}

// ---------------------------------------------------------------------------
// Kernel 0: convert weights to fp16, concat [base | spline]
// ---------------------------------------------------------------------------
__global__ void prep_kernel(const float* __restrict__ bw,
                            const float* __restrict__ sw) {
    int o = blockIdx.x;           // 0..511
    int t = threadIdx.x;          // 256 threads
    size_t rb = (size_t)o * KTOT;
    for (int k = t; k < D_IN; k += 256)
        g_W[rb + k] = __float2half(bw[o * D_IN + k]);
    const float* sp = sw + (size_t)o * (D_IN * NB);
    for (int k = t; k < D_IN * NB; k += 256)
        g_W[rb + D_IN + k] = __float2half(sp[k]);
}

// ---------------------------------------------------------------------------
// Kernel 1: layernorm + features -> fp16
// ---------------------------------------------------------------------------
__global__ void feat_kernel(const float* __restrict__ x,
                            const float* __restrict__ gamma,
                            const float* __restrict__ beta) {
    const int row = blockIdx.x;
    const int t   = threadIdx.x;        // 256 threads, 2 dims each
    const float* xr = x + (size_t)row * D_IN;

    float v0 = xr[t];
    float v1 = xr[t + 256];
    float s  = v0 + v1;
    float s2 = v0 * v0 + v1 * v1;
    #pragma unroll
    for (int off = 16; off; off >>= 1) {
        s  += __shfl_xor_sync(0xFFFFFFFFu, s,  off);
        s2 += __shfl_xor_sync(0xFFFFFFFFu, s2, off);
    }
    __shared__ float red[16];
    __shared__ float mu_s, rstd_s;
    int wid = t >> 5, lane = t & 31;
    if (lane == 0) { red[wid] = s; red[8 + wid] = s2; }
    __syncthreads();
    if (t == 0) {
        float ts = 0.f, ts2 = 0.f;
        #pragma unroll
        for (int i = 0; i < 8; i++) { ts += red[i]; ts2 += red[8 + i]; }
        float mu  = ts * (1.0f / 512.0f);
        float var = ts2 * (1.0f / 512.0f) - mu * mu;
        mu_s   = mu;
        rstd_s = rsqrtf(var + 1e-5f);
    }
    __syncthreads();
    const float mu = mu_s, rstd = rstd_s;

    size_t rb = (size_t)row * KTOT;
    const float H    = 3.0f / 5.0f;
    const float INVD = 7.0f / 3.0f;

    #pragma unroll
    for (int half = 0; half < 2; half++) {
        const int   d  = t + half * 256;
        const float xv = half ? v1 : v0;
        const float xn = (xv - mu) * rstd * gamma[d] + beta[d];

        g_F[rb + d] = __float2half(fmaxf(xn, 0.0f));

        // Cox-de Boor, uniform knots t_i = (i-3)*H - 1.5, i=0..11
        float b[11];
        #pragma unroll
        for (int i = 0; i < 11; i++) {
            float t0 = (float)(i - 3) * H - 1.5f;
            float t1 = (float)(i - 2) * H - 1.5f;
            b[i] = (xn >= t0 && xn < t1) ? 1.0f : 0.0f;
        }
        #pragma unroll
        for (int k = 1; k <= 3; k++) {
            const float inv = 1.0f / ((float)k * H);
            #pragma unroll
            for (int i = 0; i + k < 11; i++) {
                float ti   = (float)(i - 3) * H - 1.5f;
                float tik1 = (float)(i + k - 2) * H - 1.5f;
                float left  = (xn - ti) * inv;
                float right = (tik1 - xn) * inv;
                b[i] = left * b[i] + right * b[i + 1];
            }
        }

        __half oh[8];
        #pragma unroll
        for (int j = 0; j < 8; j++) {
            float g = -1.5f + (float)j * (3.0f / 7.0f);
            float u = (xn - g) * INVD;
            oh[j] = __float2half(b[j] + __expf(-u * u));
        }
        // 8 halfs = 16B; offset (512 + 8d)*2 bytes is 16B aligned
        *(uint4*)(&g_F[rb + D_IN + (size_t)d * NB]) = *(const uint4*)oh;
    }
}

// ---------------------------------------------------------------------------
// Dummy kernel: keeps ncu's -s 5 capture slot on the GEMM launch.
// ---------------------------------------------------------------------------
__global__ void align_kernel() {}

// ---------------------------------------------------------------------------
// Kernel 2: fp16 m16n8k16 GEMM, fp32 accumulators
// CTA: 128(M) x 128(N), 8 warps (4m x 2n), warp tile 32x64.
//   -> LDSM bytes/HMMA 256->192, cp.async bytes/HMMA 102->68:
//      crossbar bound (2.03 cyc/HMMA) now matches tensor bound (2.0).
// BK=64 (72 iters; per-warp work per barrier unchanged vs R13).
// 2-stage cp.async pipeline, 2 CTAs/SM.
// ---------------------------------------------------------------------------
__global__ __launch_bounds__(256, 2) void gemm_kernel(float* __restrict__ C) {
    extern __shared__ char smem[];
    const uint32_t sbase = smem_u32(smem);
    const int t    = threadIdx.x;
    const int wid  = t >> 5;
    const int wm   = wid & 3;           // m sub-tile (0..3), 32 rows
    const int wn   = wid >> 2;          // n sub-tile (0..1), 64 cols
    const int lane = t & 31;
    const int m0   = blockIdx.y * BM;
    const int n0   = blockIdx.x * BN;

    const __half* A_g = g_F + (size_t)m0 * KTOT;
    const __half* B_g = g_W + (size_t)n0 * KTOT;

    // Per-lane ldmatrix base offsets (16-bit k16 fragment maps)
    const uint32_t a_off = (uint32_t)((((lane >> 3) & 1) * 8 + (lane & 7)) * ASTRIDE
                                      + (lane >> 4) * 16);
    const uint32_t b_off = (uint32_t)((((lane >> 4) & 1) * 8 + (lane & 7)) * ASTRIDE
                                      + ((lane >> 3) & 1) * 16);

    float acc[2][8][4];
    #pragma unroll
    for (int i = 0; i < 2; i++)
        #pragma unroll
        for (int j = 0; j < 8; j++)
            #pragma unroll
            for (int q = 0; q < 4; q++) acc[i][j][q] = 0.0f;

    // ---- stage loader: 8 cp.async of 16B per thread (256 threads) ----
    // A: 128 rows x 8 chunks = 1024 units; B: 128 x 8 = 1024 units.
    auto load_stage = [&](int st, int kc) {
        const uint32_t stage = sbase + st * STG_BYTES;
        #pragma unroll
        for (int r = 0; r < 4; r++) {
            int u = t + r * 256;               // 0..1023
            int row = u >> 3, ch = u & 7;
            size_t go = (size_t)row * KTOT + kc + ch * 8;   // halfs
            uint32_t so = (uint32_t)(row * ASTRIDE + ch * 16);
            cp_async16(stage + so,           A_g + go);
            cp_async16(stage + A_BYTES + so, B_g + go);
        }
    };

    load_stage(0, 0);
    CP_COMMIT();

    for (int i = 0; i < NITER; i++) {
        if (i + 1 < NITER) {
            load_stage((i + 1) & 1, (i + 1) * BK);
            CP_COMMIT();
            CP_WAIT(1);
        } else {
            CP_WAIT(0);
        }
        __syncthreads();

        const uint32_t stage = sbase + (i & 1) * STG_BYTES;
        const uint32_t sA = stage;
        const uint32_t sB = stage + A_BYTES;
        const uint32_t awarp = (uint32_t)(wm * 32 * ASTRIDE);
        const uint32_t bwarp = (uint32_t)(wn * 64 * ASTRIDE);

        #pragma unroll
        for (int s = 0; s < 4; s++) {       // four k16 steps
            const uint32_t ks = (uint32_t)(s * 32);   // 16 fp16 = 32 bytes
            uint32_t a[2][4];
            #pragma unroll
            for (int im = 0; im < 2; im++)
                ldsm4(a[im], sA + awarp + (uint32_t)(im * 16 * ASTRIDE) + a_off + ks);
            // B fragments per 16-col group (bounds live registers)
            #pragma unroll
            for (int jj = 0; jj < 4; jj++) {
                uint32_t b[4];
                ldsm4(b, sB + bwarp + (uint32_t)(jj * 16 * ASTRIDE) + b_off + ks);
                #pragma unroll
                for (int im = 0; im < 2; im++)
                    #pragma unroll
                    for (int jh = 0; jh < 2; jh++) {
                        int j = jj * 2 + jh;
                        hmma16816(acc[im][j], a[im], b[jh * 2], b[jh * 2 + 1]);
                    }
            }
        }
        __syncthreads();   // all warps done with this stage before refill
    }

    // Writeout: row = m0 + wm*32 + im*16 + lane/4 (+8),
    //           col = n0 + wn*64 + j*8 + (lane%4)*2
    #pragma unroll
    for (int im = 0; im < 2; im++) {
        int r0 = m0 + wm * 32 + im * 16 + (lane >> 2);
        #pragma unroll
        for (int j = 0; j < 8; j++) {
            int cc = n0 + wn * 64 + j * 8 + (lane & 3) * 2;
            *(float2*)(C + (size_t)r0 * N_OUT + cc) =
                make_float2(acc[im][j][0], acc[im][j][1]);
            *(float2*)(C + (size_t)(r0 + 8) * N_OUT + cc) =
                make_float2(acc[im][j][2], acc[im][j][3]);
        }
    }
}

// ---------------------------------------------------------------------------
extern "C" void kernel_launch(void* const* d_in, const int* in_sizes, int n_in,
                              void* d_out, int out_size) {
    const float* x        = (const float*)d_in[0];
    const float* ln_gamma = (const float*)d_in[1];
    const float* ln_beta  = (const float*)d_in[2];
    const float* base_w   = (const float*)d_in[3];
    const float* spline_w = (const float*)d_in[4];
    (void)in_sizes; (void)n_in; (void)out_size;

    cudaFuncSetAttribute(gemm_kernel, cudaFuncAttributeMaxDynamicSharedMemorySize, SMEM_TOTAL);

    prep_kernel<<<N_OUT, 256>>>(base_w, spline_w);
    feat_kernel<<<M_ROWS, 256>>>(x, ln_gamma, ln_beta);
    align_kernel<<<1, 32>>>();   // keeps ncu -s 5 capture on the GEMM
    dim3 grid(N_OUT / BN, M_ROWS / BM);   // (4, 128) = 512 CTAs
    gemm_kernel<<<grid, 256, SMEM_TOTAL>>>((float*)d_out);
}